// round 9
// baseline (speedup 1.0000x reference)
#include <cuda_runtime.h>

// Encoder: out[b,e] = relu( sum_i combined[b,i] * weight[b,i,e] )
// combined = [ features[nodes[b]] , mean_j features[neigh_idx[b,j]] ]  (256 dims)
// Shapes: features [100000,128] f32, weight [4096,256,128] f32,
//         nodes [4096] i32, neigh_idx [4096,10] i32, out [4096,128] f32.
//
// Warp-autonomous design: one warp owns one batch element end-to-end.
//  - gather 11 feature rows into a private smem slice (__syncwarp only)
//  - stream the warp's 128KB weight slab row-by-row (float4/lane = 512B/row)
//  - accumulator IS the output row: no cross-warp reduce, no __syncthreads
//    anywhere, coalesced 512B store.
// Grid = 1024 CTAs x 4 warps = 4096 warps = exactly one wave on 148 SMs.

#define FEAT 128
#define EMBED 128
#define TWO_FEAT 256
#define NUM_SAMPLE 10

__global__ __launch_bounds__(128, 10)
void encoder_kernel(const float* __restrict__ features,
                    const float* __restrict__ weight,
                    const int*   __restrict__ nodes,
                    const int*   __restrict__ neigh,
                    float*       __restrict__ out)
{
    __shared__ float comb[4][TWO_FEAT];          // 4KB: per-warp slice

    const int warp = threadIdx.x >> 5;
    const int lane = threadIdx.x & 31;
    const int b = blockIdx.x * 4 + warp;          // one warp = one batch elem

    float* cw = comb[warp];

    // ---- Phase 1 (warp-local): gather self row + 10-neighbor mean.
    // lane covers dims [4*lane, 4*lane+4); each row load = 512B coalesced.
    {
        const int node = __ldg(&nodes[b]);
        const float4 sf = *reinterpret_cast<const float4*>(
            &features[(size_t)node * FEAT + lane * 4]);

        float4 m = make_float4(0.f, 0.f, 0.f, 0.f);
        #pragma unroll
        for (int j = 0; j < NUM_SAMPLE; ++j) {
            const int nb = __ldg(&neigh[b * NUM_SAMPLE + j]);
            const float4 f = *reinterpret_cast<const float4*>(
                &features[(size_t)nb * FEAT + lane * 4]);
            m.x += f.x; m.y += f.y; m.z += f.z; m.w += f.w;
        }
        const float inv = 1.0f / NUM_SAMPLE;
        reinterpret_cast<float4*>(&cw[0])[lane]    = sf;
        reinterpret_cast<float4*>(&cw[FEAT])[lane] =
            make_float4(m.x * inv, m.y * inv, m.z * inv, m.w * inv);
        __syncwarp();
    }

    // ---- Phase 2: stream this b's full weight slab (256 rows x 512B).
    // lane covers e = 4*lane..4*lane+3 for every row; acc is the output row.
    const float4* __restrict__ Wb =
        reinterpret_cast<const float4*>(weight + (size_t)b * TWO_FEAT * EMBED);

    float4 accA = make_float4(0.f, 0.f, 0.f, 0.f);
    float4 accB = make_float4(0.f, 0.f, 0.f, 0.f);

    #pragma unroll 8
    for (int k = 0; k < TWO_FEAT; k += 2) {
        const float  cA = cw[k];
        const float  cB = cw[k + 1];
        const float4 wA = __ldcs(&Wb[(size_t)k       * (EMBED / 4) + lane]);
        const float4 wB = __ldcs(&Wb[(size_t)(k + 1) * (EMBED / 4) + lane]);
        accA.x = fmaf(cA, wA.x, accA.x); accA.y = fmaf(cA, wA.y, accA.y);
        accA.z = fmaf(cA, wA.z, accA.z); accA.w = fmaf(cA, wA.w, accA.w);
        accB.x = fmaf(cB, wB.x, accB.x); accB.y = fmaf(cB, wB.y, accB.y);
        accB.z = fmaf(cB, wB.z, accB.z); accB.w = fmaf(cB, wB.w, accB.w);
    }

    // ---- relu + store (coalesced 512B per warp)
    float4 r;
    r.x = fmaxf(accA.x + accB.x, 0.0f);
    r.y = fmaxf(accA.y + accB.y, 0.0f);
    r.z = fmaxf(accA.z + accB.z, 0.0f);
    r.w = fmaxf(accA.w + accB.w, 0.0f);
    reinterpret_cast<float4*>(&out[(size_t)b * EMBED])[lane] = r;
}

extern "C" void kernel_launch(void* const* d_in, const int* in_sizes, int n_in,
                              void* d_out, int out_size)
{
    const float* features = (const float*)d_in[0];
    const float* weight   = (const float*)d_in[1];
    const int*   nodes    = (const int*)d_in[2];
    const int*   neigh    = (const int*)d_in[3];
    float*       out      = (float*)d_out;

    const int batch = in_sizes[2];      // 4096 (nodes element count)
    encoder_kernel<<<batch / 4, 128>>>(features, weight, nodes, neigh, out);
}